// round 16
// baseline (speedup 1.0000x reference)
#include <cuda_runtime.h>
#include <cstdint>

// Problem constants
constexpr int D_   = 64;      // item dim
constexpr int L_   = 16;      // code length
constexpr int NB_  = 65536;   // buckets

// Tiling: depth-3 pipeline, 4 blocks/SM (52 KB/block), 8 warps/SM
constexpr int BLOCK_ = 64;               // 2 warps
constexpr int WARPS_ = BLOCK_ / 32;
constexpr int M_     = 4;                // items per thread
constexpr int ROWSW_ = 32 * M_;          // 128 rows per warp
constexpr int TILE_  = ROWSW_ * WARPS_;  // 256 rows per block-tile
constexpr int KS_    = 16;               // k per stage (64 B per row-stage)
constexpr int ST_    = D_ / KS_;         // 4 stages per tile
constexpr int NBUF_  = 3;                // triple buffer
constexpr int STF_   = ROWSW_ * KS_;     // 2048 floats per stage buffer (8 KB)
constexpr int GRID_  = 592;              // 148 SMs x 4 resident blocks

// ---------------- f32x2 helpers ----------------
__device__ __forceinline__ uint64_t dup_f32(float x) {
    uint64_t r; asm("mov.b64 %0, {%1, %1};" : "=l"(r) : "f"(x)); return r;
}
__device__ __forceinline__ void fma2(uint64_t& a, uint64_t b, uint64_t c) {
    asm("fma.rn.f32x2 %0, %1, %2, %0;" : "+l"(a) : "l"(b), "l"(c));
}
__device__ __forceinline__ void unpack2(uint64_t v, float& lo, float& hi) {
    asm("mov.b64 {%0, %1}, %2;" : "=f"(lo), "=f"(hi) : "l"(v));
}
__device__ __forceinline__ void cp_async16(void* d, const void* s) {
    unsigned a = (unsigned)__cvta_generic_to_shared(d);
    asm volatile("cp.async.cg.shared.global [%0], [%1], 16;" :: "r"(a), "l"(s));
}
__device__ __forceinline__ void cp_commit() {
    asm volatile("cp.async.commit_group;" ::: "memory");
}
template<int N>
__device__ __forceinline__ void cp_wait() {
    asm volatile("cp.async.wait_group %0;" :: "n"(N) : "memory");
}

// ---------------- counts init (vectorized: 65536 floats = 16384 float4) ----
__global__ void init_counts_kernel(float4* __restrict__ outCounts,
                                   const float4* __restrict__ counts) {
    int i = blockIdx.x * blockDim.x + threadIdx.x;   // 128 x 128 = 16384
    outCounts[i] = counts[i];
}

// ---------------- generic per-item kernel (tail / fallback layouts) -------
__global__ void hash_tail_kernel(const float* __restrict__ items,
                                 const float* __restrict__ W,
                                 float* __restrict__ outBuckets,
                                 float* __restrict__ outCounts,
                                 int start, int n, int asInt) {
    int gi = start + blockIdx.x * blockDim.x + threadIdx.x;
    if (gi >= n) return;
    const float* row = items + (size_t)gi * D_;
    float dot[L_];
    #pragma unroll
    for (int j = 0; j < L_; ++j) dot[j] = 0.0f;
    for (int k = 0; k < D_; ++k) {
        float v = row[k];
        #pragma unroll
        for (int j = 0; j < L_; ++j) dot[j] = fmaf(v, W[k * L_ + j], dot[j]);
    }
    unsigned b = 0;
    #pragma unroll
    for (int j = 0; j < L_; ++j)
        if (dot[j] >= 0.0f) b |= 1u << (L_ - 1 - j);
    if (outBuckets) {
        if (asInt) reinterpret_cast<int*>(outBuckets)[gi] = (int)b;
        else       outBuckets[gi] = (float)b;
    }
    if (outCounts) atomicAdd(&outCounts[b], 1.0f);
}

// ---------------- main kernel (expected layout only) ----------------
__global__ __launch_bounds__(BLOCK_)
void hash_counter_kernel(const float* __restrict__ items,
                         const float* __restrict__ W,
                         float* __restrict__ outBuckets,
                         float* __restrict__ outCounts,
                         int nTiles) {
    // Per warp: three 8 KB stage buffers. Row r (0..127) holds 16 floats;
    // 16B-chunk c (0..3) at unit (r*4 + (c ^ ((r>>1)&3))).
    // Conflict-free for coalesced stores and strided consumer reads.
    __shared__ __align__(128) float sIt[WARPS_][NBUF_][STF_];
    __shared__ __align__(16)  float sW[D_ * L_];

    const int tid = threadIdx.x;
    const int w   = tid >> 5;
    const int l   = tid & 31;
    const int bid = blockIdx.x;

    const int nMy = (nTiles - bid + GRID_ - 1) / GRID_;   // tiles for this block
    if (nMy <= 0) return;

    for (int i = tid; i < D_ * L_; i += BLOCK_) sW[i] = W[i];
    __syncthreads();

    // ---- loader constants ----
    // lane l writes float4 idx = l + 32i: row = (l>>2)+8i, c = l&3.
    // scol = c ^ ((row>>1)&3) = (l&3) ^ ((l>>3)&3)  (8i doesn't touch bits 1-2)
    const int scolL = (l & 3) ^ ((l >> 3) & 3);
    float* const smL0 = &sIt[w][0][(l >> 2) * KS_ + scolL * 4];
    const size_t rowOff = (size_t)(w * ROWSW_ + (l >> 2)) * D_ + (l & 3) * 4;

    // ---- consumer constants ----
    // thread reads rows 32m+l: byte = 2048m + 64l + 16*(c ^ ((l>>1)&3))
    const char* const cb0 = (const char*)&sIt[w][0][0];
    unsigned coff[M_];
    {
        const unsigned z = (((unsigned)l >> 1) & 3u) << 4;
        #pragma unroll
        for (int m = 0; m < M_; ++m)
            coff[m] = (unsigned)(2048 * m + 64 * l) + z;
    }

    // ---- cross-tile load cursor ----
    const size_t tileStride = (size_t)GRID_ * TILE_ * D_;
    const float* pL = items + (size_t)bid * TILE_ * D_ + rowOff;
    int sL = 0;                        // stage-within-tile of load cursor
    int qL = 0;                        // stages issued
    const int qTot = nMy * ST_;

    auto issue = [&](int buf) {
        if (qL < qTot) {
            float* sm = smL0 + buf * STF_;
            #pragma unroll
            for (int i = 0; i < 16; ++i)          // 128 rows = 16 x 8 rows
                cp_async16(sm + i * 128, pL + (size_t)i * 8 * D_);
            if (sL == ST_ - 1) { sL = 0; pL += tileStride - (ST_ - 1) * KS_; }
            else               { ++sL;  pL += KS_; }
            ++qL;
        }
        cp_commit();                   // empty groups at stream end are fine
    };

    auto compute_stage = [&](int s, int buf, uint64_t (&acc)[M_][8]) {
        const char* cbuf = cb0 + buf * (STF_ * 4);
        #pragma unroll
        for (int c = 0; c < 4; ++c) {
            float4 v[M_];
            #pragma unroll
            for (int m = 0; m < M_; ++m)
                v[m] = *reinterpret_cast<const float4*>(
                           cbuf + (coff[m] ^ (unsigned)(c << 4)));
            #pragma unroll
            for (int kk = 0; kk < 4; ++kk) {
                const int k = s * KS_ + c * 4 + kk;
                const ulonglong2* wr =
                    reinterpret_cast<const ulonglong2*>(&sW[k * L_]);
                ulonglong2 wA = wr[0], wB = wr[1], wC = wr[2], wD = wr[3];
                uint64_t wq[8] = {wA.x, wA.y, wB.x, wB.y, wC.x, wC.y, wD.x, wD.y};
                #pragma unroll
                for (int m = 0; m < M_; ++m) {
                    float vk = (kk == 0) ? v[m].x : (kk == 1) ? v[m].y
                             : (kk == 2) ? v[m].z : v[m].w;
                    uint64_t dv = dup_f32(vk);
                    #pragma unroll
                    for (int j = 0; j < 8; ++j) fma2(acc[m][j], dv, wq[j]);
                }
            }
        }
    };

    // Prologue: 3 stages in flight
    issue(0); issue(1); issue(2);

    uint64_t acc[M_][8];
    int tAct = bid;
    int bufc = 0;                      // buffer ring cursor (stage s uses bufc)

    for (int tt = 0; tt < nMy; ++tt) {
        #pragma unroll
        for (int m = 0; m < M_; ++m)
            #pragma unroll
            for (int j = 0; j < 8; ++j) acc[m][j] = 0ull;

        #pragma unroll
        for (int s = 0; s < ST_; ++s) {
            cp_wait<2>(); __syncwarp();          // stage s landed (depth 3)
            compute_stage(s, bufc, acc);
            __syncwarp(); issue(bufc);           // refill with stage s+3
            if (++bufc == NBUF_) bufc = 0;
        }

        // epilogue overlaps already-issued loads (32-bit indices)
        const int giBase = tAct * TILE_ + w * ROWSW_ + l;
        #pragma unroll
        for (int m = 0; m < M_; ++m) {
            int gi = giBase + 32 * m;
            unsigned b = 0;
            #pragma unroll
            for (int j = 0; j < 8; ++j) {
                float lo, hi;
                unpack2(acc[m][j], lo, hi);
                if (lo >= 0.0f) b |= 1u << (15 - 2 * j);
                if (hi >= 0.0f) b |= 1u << (14 - 2 * j);
            }
            outBuckets[gi] = (float)b;
            atomicAdd(&outCounts[b], 1.0f);
        }
        tAct += GRID_;
    }
}

// ---------------- launch ----------------
extern "C" void kernel_launch(void* const* d_in, const int* in_sizes, int n_in,
                              void* d_out, int out_size) {
    const float* items  = (const float*)d_in[0];
    const float* W      = (const float*)d_in[1];
    const float* counts = (const float*)d_in[2];
    const int n = in_sizes[0] / D_;

    float* out = (float*)d_out;

    if (out_size >= n + NB_) {
        // expected layout: concatenated (buckets f32[n], counts f32[NB])
        float* outBuckets = out;
        float* outCounts  = out + n;
        init_counts_kernel<<<128, 128>>>((float4*)outCounts,
                                         (const float4*)counts);

        const int nTiles = n / TILE_;
        const int rem    = n - nTiles * TILE_;
        if (nTiles > 0)
            hash_counter_kernel<<<GRID_, BLOCK_>>>(items, W, outBuckets,
                                                   outCounts, nTiles);
        if (rem > 0)
            hash_tail_kernel<<<(rem + 127) / 128, 128>>>(items, W, outBuckets,
                                                         outCounts,
                                                         nTiles * TILE_, n, 0);
    } else if (out_size == NB_) {       // counts only
        init_counts_kernel<<<128, 128>>>((float4*)out, (const float4*)counts);
        hash_tail_kernel<<<(n + 127) / 128, 128>>>(items, W, nullptr, out,
                                                   0, n, 0);
    } else {                            // buckets only -> int32
        hash_tail_kernel<<<(n + 127) / 128, 128>>>(items, W, out, nullptr,
                                                   0, n, 1);
    }
}

// round 17
// speedup vs baseline: 1.0709x; 1.0709x over previous
#include <cuda_runtime.h>
#include <cstdint>

// Problem constants
constexpr int D_   = 64;      // item dim
constexpr int L_   = 16;      // code length
constexpr int NB_  = 65536;   // buckets

// Tiling (R6/R11 proven config: 6 blocks/SM with margin, 12 warps/SM)
constexpr int BLOCK_ = 64;               // 2 warps
constexpr int WARPS_ = BLOCK_ / 32;
constexpr int M_     = 4;                // items per thread
constexpr int ROWSW_ = 32 * M_;          // 128 rows per warp
constexpr int TILE_  = ROWSW_ * WARPS_;  // 256 rows per block-tile
constexpr int KS_    = 16;               // k per stage (64 B per row-stage)
constexpr int ST_    = D_ / KS_;         // 4 stages per tile
constexpr int STF_   = ROWSW_ * KS_;     // 2048 floats per stage buffer (8 KB)
constexpr int GRID_  = 888;              // 148 SMs x 6 resident blocks

// ---------------- f32x2 helpers ----------------
__device__ __forceinline__ uint64_t dup_f32(float x) {
    uint64_t r; asm("mov.b64 %0, {%1, %1};" : "=l"(r) : "f"(x)); return r;
}
__device__ __forceinline__ void fma2(uint64_t& a, uint64_t b, uint64_t c) {
    asm("fma.rn.f32x2 %0, %1, %2, %0;" : "+l"(a) : "l"(b), "l"(c));
}
__device__ __forceinline__ void unpack2(uint64_t v, float& lo, float& hi) {
    asm("mov.b64 {%0, %1}, %2;" : "=f"(lo), "=f"(hi) : "l"(v));
}
__device__ __forceinline__ void cp_async16(void* d, const void* s) {
    unsigned a = (unsigned)__cvta_generic_to_shared(d);
    asm volatile("cp.async.cg.shared.global [%0], [%1], 16;" :: "r"(a), "l"(s));
}
__device__ __forceinline__ void cp_commit() {
    asm volatile("cp.async.commit_group;" ::: "memory");
}
template<int N>
__device__ __forceinline__ void cp_wait() {
    asm volatile("cp.async.wait_group %0;" :: "n"(N) : "memory");
}

// ---------------- counts init (vectorized: 65536 floats = 16384 float4) ----
__global__ void init_counts_kernel(float4* __restrict__ outCounts,
                                   const float4* __restrict__ counts) {
    int i = blockIdx.x * blockDim.x + threadIdx.x;   // 128 x 128 = 16384
    outCounts[i] = counts[i];
}

// ---------------- generic per-item kernel (tail / fallback layouts) -------
__global__ void hash_tail_kernel(const float* __restrict__ items,
                                 const float* __restrict__ W,
                                 float* __restrict__ outBuckets,
                                 float* __restrict__ outCounts,
                                 int start, int n, int asInt) {
    int gi = start + blockIdx.x * blockDim.x + threadIdx.x;
    if (gi >= n) return;
    const float* row = items + (size_t)gi * D_;
    float dot[L_];
    #pragma unroll
    for (int j = 0; j < L_; ++j) dot[j] = 0.0f;
    for (int k = 0; k < D_; ++k) {
        float v = row[k];
        #pragma unroll
        for (int j = 0; j < L_; ++j) dot[j] = fmaf(v, W[k * L_ + j], dot[j]);
    }
    unsigned b = 0;
    #pragma unroll
    for (int j = 0; j < L_; ++j)
        if (dot[j] >= 0.0f) b |= 1u << (L_ - 1 - j);
    if (outBuckets) {
        if (asInt) reinterpret_cast<int*>(outBuckets)[gi] = (int)b;
        else       outBuckets[gi] = (float)b;
    }
    if (outCounts) atomicAdd(&outCounts[b], 1.0f);
}

// ---------------- main kernel (expected layout only) ----------------
__global__ __launch_bounds__(BLOCK_, 6)
void hash_counter_kernel(const float* __restrict__ items,
                         const float* __restrict__ W,
                         float* __restrict__ outBuckets,
                         float* __restrict__ outCounts,
                         int nTiles) {
    // Per warp: two 8 KB stage buffers. Row r (0..127) holds 16 floats;
    // 16B-chunk c (0..3) at unit (r*4 + (c ^ ((r>>1)&3))).
    // Conflict-free for coalesced stores and strided consumer reads.
    __shared__ __align__(128) float sIt[WARPS_][2][STF_];
    __shared__ __align__(16)  float sW[D_ * L_];

    const int tid = threadIdx.x;
    const int w   = tid >> 5;
    const int l   = tid & 31;
    const int bid = blockIdx.x;

    const int nMy = (nTiles - bid + GRID_ - 1) / GRID_;   // tiles for this block
    if (nMy <= 0) return;

    for (int i = tid; i < D_ * L_; i += BLOCK_) sW[i] = W[i];
    __syncthreads();

    // ---- loader constants ----
    // lane l writes float4 idx = l + 32i: row = (l>>2)+8i, c = l&3.
    // scol = c ^ ((row>>1)&3) = (l&3) ^ ((l>>3)&3)  (8i doesn't touch bits 1-2)
    const int scolL = (l & 3) ^ ((l >> 3) & 3);
    float* const smL0 = &sIt[w][0][(l >> 2) * KS_ + scolL * 4];
    const size_t rowOff = (size_t)(w * ROWSW_ + (l >> 2)) * D_ + (l & 3) * 4;

    // ---- consumer constants ----
    // thread reads rows 32m+l: byte = 2048m + 64l + 16*(c ^ ((l>>1)&3))
    const char* const cb0 = (const char*)&sIt[w][0][0];
    unsigned coff[M_];
    {
        const unsigned z = (((unsigned)l >> 1) & 3u) << 4;
        #pragma unroll
        for (int m = 0; m < M_; ++m)
            coff[m] = (unsigned)(2048 * m + 64 * l) + z;
    }

    // ---- cross-tile load cursor ----
    const size_t tileStride = (size_t)GRID_ * TILE_ * D_;
    const float* pL = items + (size_t)bid * TILE_ * D_ + rowOff;
    int sL = 0;                        // stage-within-tile of load cursor
    int qL = 0;                        // stages issued
    const int qTot = nMy * ST_;

    auto issue = [&](int buf) {
        if (qL < qTot) {
            float* sm = smL0 + buf * STF_;
            #pragma unroll
            for (int i = 0; i < 16; ++i)          // 128 rows = 16 x 8 rows
                cp_async16(sm + i * 128, pL + (size_t)i * 8 * D_);
            if (sL == ST_ - 1) { sL = 0; pL += tileStride - (ST_ - 1) * KS_; }
            else               { ++sL;  pL += KS_; }
            ++qL;
        }
        cp_commit();                   // empty groups at stream end are fine
    };

    auto loadW = [&](uint64_t (&wq)[8], int k) {
        const ulonglong2* wr = reinterpret_cast<const ulonglong2*>(&sW[k * L_]);
        ulonglong2 wA = wr[0], wB = wr[1], wC = wr[2], wD = wr[3];
        wq[0] = wA.x; wq[1] = wA.y; wq[2] = wB.x; wq[3] = wB.y;
        wq[4] = wC.x; wq[5] = wC.y; wq[6] = wD.x; wq[7] = wD.y;
    };

    // Flattened kk loop with double-buffered W rows: while fma-ing row kk,
    // row kk+1's LDS are in flight (load->use distance ~36 instrs vs ~0).
    auto compute_stage = [&](int s, int buf, uint64_t (&acc)[M_][8]) {
        const char* cbuf = cb0 + buf * (STF_ * 4);
        uint64_t wq[2][8];
        float4 v[M_];
        loadW(wq[0], s * KS_);
        #pragma unroll
        for (int m = 0; m < M_; ++m)
            v[m] = *reinterpret_cast<const float4*>(cbuf + coff[m]);
        #pragma unroll
        for (int kk = 0; kk < 16; ++kk) {
            if (kk < 15) loadW(wq[(kk + 1) & 1], s * KS_ + kk + 1);
            const uint64_t (&wqc)[8] = wq[kk & 1];
            #pragma unroll
            for (int m = 0; m < M_; ++m) {
                const int ph = kk & 3;
                float vk = (ph == 0) ? v[m].x : (ph == 1) ? v[m].y
                         : (ph == 2) ? v[m].z : v[m].w;
                uint64_t dv = dup_f32(vk);
                #pragma unroll
                for (int j = 0; j < 8; ++j) fma2(acc[m][j], dv, wqc[j]);
            }
            if ((kk & 3) == 3 && kk < 15) {
                const unsigned cx = (unsigned)(((kk + 1) >> 2) << 4);
                #pragma unroll
                for (int m = 0; m < M_; ++m)
                    v[m] = *reinterpret_cast<const float4*>(
                               cbuf + (coff[m] ^ cx));
            }
        }
    };

    issue(0);
    issue(1);

    uint64_t acc[M_][8];
    int tAct = bid;

    for (int tt = 0; tt < nMy; ++tt) {
        #pragma unroll
        for (int m = 0; m < M_; ++m)
            #pragma unroll
            for (int j = 0; j < 8; ++j) acc[m][j] = 0ull;

        #pragma unroll
        for (int s = 0; s < ST_; ++s) {
            cp_wait<1>(); __syncwarp();
            compute_stage(s, s & 1, acc);
            __syncwarp(); issue(s & 1);
        }

        // epilogue overlaps already-issued next-tile loads (32-bit indices)
        const int giBase = tAct * TILE_ + w * ROWSW_ + l;
        #pragma unroll
        for (int m = 0; m < M_; ++m) {
            int gi = giBase + 32 * m;
            unsigned b = 0;
            #pragma unroll
            for (int j = 0; j < 8; ++j) {
                float lo, hi;
                unpack2(acc[m][j], lo, hi);
                if (lo >= 0.0f) b |= 1u << (15 - 2 * j);
                if (hi >= 0.0f) b |= 1u << (14 - 2 * j);
            }
            outBuckets[gi] = (float)b;
            atomicAdd(&outCounts[b], 1.0f);
        }
        tAct += GRID_;
    }
}

// ---------------- launch ----------------
extern "C" void kernel_launch(void* const* d_in, const int* in_sizes, int n_in,
                              void* d_out, int out_size) {
    const float* items  = (const float*)d_in[0];
    const float* W      = (const float*)d_in[1];
    const float* counts = (const float*)d_in[2];
    const int n = in_sizes[0] / D_;

    float* out = (float*)d_out;

    if (out_size >= n + NB_) {
        // expected layout: concatenated (buckets f32[n], counts f32[NB])
        float* outBuckets = out;
        float* outCounts  = out + n;
        init_counts_kernel<<<128, 128>>>((float4*)outCounts,
                                         (const float4*)counts);

        const int nTiles = n / TILE_;
        const int rem    = n - nTiles * TILE_;
        if (nTiles > 0)
            hash_counter_kernel<<<GRID_, BLOCK_>>>(items, W, outBuckets,
                                                   outCounts, nTiles);
        if (rem > 0)
            hash_tail_kernel<<<(rem + 127) / 128, 128>>>(items, W, outBuckets,
                                                         outCounts,
                                                         nTiles * TILE_, n, 0);
    } else if (out_size == NB_) {       // counts only
        init_counts_kernel<<<128, 128>>>((float4*)out, (const float4*)counts);
        hash_tail_kernel<<<(n + 127) / 128, 128>>>(items, W, nullptr, out,
                                                   0, n, 0);
    } else {                            // buckets only -> int32
        hash_tail_kernel<<<(n + 127) / 128, 128>>>(items, W, out, nullptr,
                                                   0, n, 1);
    }
}